// round 17
// baseline (speedup 1.0000x reference)
#include <cuda_runtime.h>
#include <cstdint>

// MXFP8 E4M3 quantize->dequantize, 32-element blocks along last axis.
// R16: final A/B on CTA granularity — identical body to R15 (the 3x-
// reproduced best: 74.5us kernel, DRAM 82.4%, 6.53 TB/s) but block=256 /
// grid=16384. The session-winning mechanism is fresh-CTA load front-
// batching; finer CTA granularity doubles fresh-CTA arrival rate and
// smooths the tail wave. __launch_bounds__(256,8) holds the 32-reg /
// 100%-theoretical-occupancy point.
//
// Winning invariant (R2..R15):
//   * lane-contiguous LDG.E.256 (nL<=8 per instr)
//   * 2 front-batched 256-bit loads per thread (16 lines in flight/warp)
//   * 32 regs -> full theoretical residency
//   * many-short-CTA launch grid (persistence loses MLP)
//   * MX block spans 2 lanes -> single shfl.xor(1) per 32-float block
//
// All scales are exact powers of two built by bit manipulation; rel_err
// has been 0.0 on every round.

static constexpr int EMAX = 8;           // e4m3
static constexpr float MAX_NORM = 448.0f;

__device__ __forceinline__ void ldg256cs(const float* p, float* v) {
    asm volatile(
        "ld.global.cs.v8.f32 {%0,%1,%2,%3,%4,%5,%6,%7}, [%8];"
        : "=f"(v[0]), "=f"(v[1]), "=f"(v[2]), "=f"(v[3]),
          "=f"(v[4]), "=f"(v[5]), "=f"(v[6]), "=f"(v[7])
        : "l"(p));
}

__device__ __forceinline__ void stg256cs(float* p, const float* v) {
    asm volatile(
        "st.global.cs.v8.f32 [%0], {%1,%2,%3,%4,%5,%6,%7,%8};"
        :: "l"(p),
           "f"(v[0]), "f"(v[1]), "f"(v[2]), "f"(v[3]),
           "f"(v[4]), "f"(v[5]), "f"(v[6]), "f"(v[7])
        : "memory");
}

__device__ __forceinline__ float quant_e4m3(float x, float iscale, float scale) {
    float a = x * iscale;                          // exact (iscale = 2^k)
    uint32_t au = __float_as_uint(a);
    uint32_t ab = au & 0x7fffffffu;                // |a|
    int pe = (int)(ab >> 23) - 127;                // floor(log2|a|), exact for normals
    pe = max(pe, -6);                              // MIN_EXP (denorm region clamp)
    // lshift = 2^(3-pe), inv_lshift = 2^(pe-3); pe in [-6, 8] -> both normal
    float lsh  = __uint_as_float((uint32_t)(130 - pe) << 23);
    float ilsh = __uint_as_float((uint32_t)(124 + pe) << 23);
    // round-half-away-from-zero on magnitude: product is exact, +0.5 rounds once
    float r = floorf(__uint_as_float(ab) * lsh + 0.5f);
    float m = fminf(r * ilsh, MAX_NORM);           // saturate to e4m3 max normal
    float res = m * scale;
    return __uint_as_float(__float_as_uint(res) | (au & 0x80000000u));
}

__global__ void __launch_bounds__(256, 8) mxq_kernel(const float* __restrict__ in,
                                                     float* __restrict__ out) {
    int gid = blockIdx.x * blockDim.x + threadIdx.x;
    long base = (long)gid * 16;                    // 16 contiguous floats

    // Front-batched 256-bit loads (16 lines in flight per warp)
    float a[8], b[8];
    ldg256cs(in + base, a);
    ldg256cs(in + base + 8, b);

    // amax over this thread's 16, then one shfl across the 2-lane block group
    float m = fmaxf(fabsf(a[0]), fabsf(a[1]));
    m = fmaxf(m, fmaxf(fabsf(a[2]), fabsf(a[3])));
    m = fmaxf(m, fmaxf(fabsf(a[4]), fabsf(a[5])));
    m = fmaxf(m, fmaxf(fabsf(a[6]), fabsf(a[7])));
    m = fmaxf(m, fmaxf(fabsf(b[0]), fabsf(b[1])));
    m = fmaxf(m, fmaxf(fabsf(b[2]), fabsf(b[3])));
    m = fmaxf(m, fmaxf(fabsf(b[4]), fabsf(b[5])));
    m = fmaxf(m, fmaxf(fabsf(b[6]), fabsf(b[7])));
    m = fmaxf(m, __shfl_xor_sync(0xffffffffu, m, 1));

    int e = (int)(__float_as_uint(m) >> 23);       // m >= 0, no sign bit
    int se = e - 127 - EMAX;
    se = max(se, -127);
    float scale  = __uint_as_float((uint32_t)(se + 127) << 23);
    float iscale = __uint_as_float((uint32_t)(127 - se) << 23);

    // Process + store first half (registers retire early), then second half.
#pragma unroll
    for (int i = 0; i < 8; i++) a[i] = quant_e4m3(a[i], iscale, scale);
    stg256cs(out + base, a);
#pragma unroll
    for (int i = 0; i < 8; i++) b[i] = quant_e4m3(b[i], iscale, scale);
    stg256cs(out + base + 8, b);
}

extern "C" void kernel_launch(void* const* d_in, const int* in_sizes, int n_in,
                              void* d_out, int out_size) {
    const float* in = (const float*)d_in[0];
    float* out = (float*)d_out;
    int n = out_size;                              // 67,108,864 floats
    int threads = 256;
    int total_threads = n / 16;                    // 4,194,304
    int blocks = total_threads / threads;          // 16384
    mxq_kernel<<<blocks, threads>>>(in, out);
}